// round 9
// baseline (speedup 1.0000x reference)
#include <cuda_runtime.h>
#include <cstdint>

// LIF recurrence over 4 timesteps (forward value only):
//   mem = 0.25*mem + x[t]; spike = mem > 0.5; out[t] = spike; mem = spike ? 0 : mem
//
// x/out: [T=4, N=8388608] fp32.
// R8: split the 1R:1W mixed stream (pinned at ~5.7 TB/s, DRAM ~70%, across 5
// kernel variants) into two direction-pure passes:
//   pass 1: read x (128 MiB) -> bit-packed spikes (4 MiB scratch)   [~pure read]
//   pass 2: read bits (L2-resident) -> expand -> write out (128 MiB) [~pure write]
// Direction-pure streams avoid DRAM R/W bus turnaround; same total traffic.

static constexpr float DECAY  = 0.25f;
static constexpr float THRESH = 0.5f;   // V_TH=1: mem/V_TH > 0.5 <=> mem > 0.5

static constexpr int N_ELEM = 8388608;       // elements per timestep
static constexpr int N8     = N_ELEM / 8;    // v8 groups per timestep = 1,048,576

// 32 spike bits per v8-group (8 elems x 4 timesteps) -> 4 MiB scratch.
__device__ uint32_t g_spike_bits[N8];

struct f8 { float v[8]; };

__device__ __forceinline__ f8 ldg256_cs(const float* p) {
    f8 r;
    asm volatile(
        "ld.global.cs.v8.f32 {%0,%1,%2,%3,%4,%5,%6,%7}, [%8];"
        : "=f"(r.v[0]), "=f"(r.v[1]), "=f"(r.v[2]), "=f"(r.v[3]),
          "=f"(r.v[4]), "=f"(r.v[5]), "=f"(r.v[6]), "=f"(r.v[7])
        : "l"(p));
    return r;
}

__device__ __forceinline__ void stg256_cs(float* p, const f8& r) {
    asm volatile(
        "st.global.cs.v8.f32 [%0], {%1,%2,%3,%4,%5,%6,%7,%8};"
        :: "l"(p),
           "f"(r.v[0]), "f"(r.v[1]), "f"(r.v[2]), "f"(r.v[3]),
           "f"(r.v[4]), "f"(r.v[5]), "f"(r.v[6]), "f"(r.v[7])
        : "memory");
}

// ---------------- pass 1: compute, bit-pack ----------------
__global__ __launch_bounds__(256)
void lif_pass1(const float* __restrict__ x) {
    const int i = blockIdx.x * blockDim.x + threadIdx.x;
    if (i >= N8) return;
    const size_t e = (size_t)i * 8;

    f8 v0 = ldg256_cs(x + (size_t)0 * N_ELEM + e);
    f8 v1 = ldg256_cs(x + (size_t)1 * N_ELEM + e);
    f8 v2 = ldg256_cs(x + (size_t)2 * N_ELEM + e);
    f8 v3 = ldg256_cs(x + (size_t)3 * N_ELEM + e);

    uint32_t bits = 0;
    #pragma unroll
    for (int k = 0; k < 8; ++k) {
        float mem = 0.f;
        const float xs[4] = { v0.v[k], v1.v[k], v2.v[k], v3.v[k] };
        #pragma unroll
        for (int t = 0; t < 4; ++t) {
            mem = fmaf(mem, DECAY, xs[t]);
            bool s = mem > THRESH;
            if (s) bits |= 1u << (t * 8 + k);
            mem = s ? 0.f : mem;
        }
    }
    // Default store: cache in L2 so pass 2 reads hit L2 (4 MiB << 126 MB).
    g_spike_bits[i] = bits;
}

// ---------------- pass 2: expand bits -> fp32 out ----------------
__global__ __launch_bounds__(256)
void lif_pass2(float* __restrict__ out) {
    const int i = blockIdx.x * blockDim.x + threadIdx.x;
    if (i >= N8) return;
    const size_t e = (size_t)i * 8;

    const uint32_t bits = g_spike_bits[i];   // L2 hit

    #pragma unroll
    for (int t = 0; t < 4; ++t) {
        f8 sp;
        #pragma unroll
        for (int k = 0; k < 8; ++k)
            sp.v[k] = (bits >> (t * 8 + k)) & 1u ? 1.f : 0.f;
        stg256_cs(out + (size_t)t * N_ELEM + e, sp);
    }
}

extern "C" void kernel_launch(void* const* d_in, const int* in_sizes, int n_in,
                              void* d_out, int out_size) {
    const float* x = (const float*)d_in[0];
    float* out = (float*)d_out;

    const int threads = 256;
    const int blocks = (N8 + threads - 1) / threads;   // 4096

    lif_pass1<<<blocks, threads>>>(x);
    lif_pass2<<<blocks, threads>>>(out);
}

// round 10
// speedup vs baseline: 1.1468x; 1.1468x over previous
#include <cuda_runtime.h>
#include <cstdint>

// LIF recurrence over 4 timesteps (forward value only):
//   mem = 0.25*mem + x[t]; spike = mem > 0.5; out[t] = spike; mem = spike ? 0 : mem
//
// x/out: [T=4, N=8388608] fp32. Fused single kernel (two-pass split pays 2x
// replay overhead and pure-write streams run at only ~3.5 TB/s -> R8 regressed).
// Mixed 1R:1W stream at ~7.1 TB/s app-effective = 89% of HBM spec; near ceiling.
// R9: reads via non-coherent path (ld.global.nc.cs.v8.f32), stores st.global.cs
// (measured best in R5 A/B). Otherwise identical to best kernel (R7).

static constexpr float DECAY  = 0.25f;
static constexpr float THRESH = 0.5f;   // V_TH=1: mem/V_TH > 0.5 <=> mem > 0.5

struct f8 { float v[8]; };

__device__ __forceinline__ f8 ldg256_nc_cs(const float* p) {
    f8 r;
    asm volatile(
        "ld.global.nc.cs.v8.f32 {%0,%1,%2,%3,%4,%5,%6,%7}, [%8];"
        : "=f"(r.v[0]), "=f"(r.v[1]), "=f"(r.v[2]), "=f"(r.v[3]),
          "=f"(r.v[4]), "=f"(r.v[5]), "=f"(r.v[6]), "=f"(r.v[7])
        : "l"(p));
    return r;
}

__device__ __forceinline__ void stg256_cs(float* p, const f8& r) {
    asm volatile(
        "st.global.cs.v8.f32 [%0], {%1,%2,%3,%4,%5,%6,%7,%8};"
        :: "l"(p),
           "f"(r.v[0]), "f"(r.v[1]), "f"(r.v[2]), "f"(r.v[3]),
           "f"(r.v[4]), "f"(r.v[5]), "f"(r.v[6]), "f"(r.v[7])
        : "memory");
}

__device__ __forceinline__ void lif_step(float& mem, const float x, float& sp) {
    mem = fmaf(mem, DECAY, x);
    bool s = mem > THRESH;
    sp  = s ? 1.f : 0.f;
    mem = s ? 0.f : mem;
}

__device__ __forceinline__ void lif_step8(f8& mem, f8& io /* in: x, out: spike */) {
    #pragma unroll
    for (int k = 0; k < 8; ++k)
        lif_step(mem.v[k], io.v[k], io.v[k]);
}

__global__ __launch_bounds__(256)
void lif_kernel(const float* __restrict__ x, float* __restrict__ out, int n8) {
    const int i = blockIdx.x * blockDim.x + threadIdx.x;
    if (i >= n8) return;

    const size_t e = (size_t)i * 8;          // element offset within a timestep
    const size_t n = (size_t)n8 * 8;         // elements per timestep

    // ---- read phase: 4 independent 256-bit nc loads in flight ----
    f8 v0 = ldg256_nc_cs(x + 0 * n + e);
    f8 v1 = ldg256_nc_cs(x + 1 * n + e);
    f8 v2 = ldg256_nc_cs(x + 2 * n + e);
    f8 v3 = ldg256_nc_cs(x + 3 * n + e);

    // ---- compute: sequential recurrence in registers ----
    f8 mem;
    #pragma unroll
    for (int k = 0; k < 8; ++k) mem.v[k] = 0.f;
    lif_step8(mem, v0);
    lif_step8(mem, v1);
    lif_step8(mem, v2);
    lif_step8(mem, v3);

    // ---- write phase: batched 256-bit evict-first stores ----
    stg256_cs(out + 0 * n + e, v0);
    stg256_cs(out + 1 * n + e, v1);
    stg256_cs(out + 2 * n + e, v2);
    stg256_cs(out + 3 * n + e, v3);
}

extern "C" void kernel_launch(void* const* d_in, const int* in_sizes, int n_in,
                              void* d_out, int out_size) {
    const float* x = (const float*)d_in[0];
    float* out = (float*)d_out;

    const int total = in_sizes[0];          // T*N = 33,554,432
    const int n = total / 4;                // N per timestep = 8,388,608
    const int n8 = n / 8;                   // v8 groups per timestep = 1,048,576

    const int threads = 256;
    const int blocks = (n8 + threads - 1) / threads;   // 4096

    lif_kernel<<<blocks, threads>>>(x, out, n8);
}